// round 2
// baseline (speedup 1.0000x reference)
#include <cuda_runtime.h>

#define P_DIM 1024
#define Q_DIM 1024
#define S_DIM 128
#define B_DIM 8

#define TP 32
#define TQ 32
#define PADP (TP + 1)
#define PADQ (TQ + 1)

// Precomputed projections (device-global scratch: allocation-free rule)
__device__ float g_pr[P_DIM * S_DIM];  // product @ w1[:S]   [P, S]
__device__ float g_pe[Q_DIM * S_DIM];  // person  @ w1[S:]   [Q, S]

// ---------------------------------------------------------------------------
// Kernel 1: tiny projections. grid (1024, 2), block 128.
// blockIdx.y == 0 -> pr row, == 1 -> pe row. w1 is [2S, S] row-major.
// ---------------------------------------------------------------------------
__global__ __launch_bounds__(S_DIM) void proj_kernel(
    const float* __restrict__ product, const float* __restrict__ person,
    const float* __restrict__ w1) {
  __shared__ float rowbuf[S_DIM];
  const int row = blockIdx.x;
  const int s = threadIdx.x;
  const float* src;
  const float* wb;
  float* dst;
  if (blockIdx.y == 0) {
    src = product; wb = w1;                  dst = g_pr;
  } else {
    src = person;  wb = w1 + S_DIM * S_DIM;  dst = g_pe;
  }
  rowbuf[s] = src[row * S_DIM + s];
  __syncthreads();
  float acc = 0.f;
#pragma unroll 8
  for (int k = 0; k < S_DIM; ++k)
    acc = fmaf(rowbuf[k], wb[k * S_DIM + s], acc);  // w1 coalesced over s, L1-resident
  dst[row * S_DIM + s] = acc;
}

// Numerically stable softplus: max(z,0) + log1p(exp(-|z|)). 2 MUFU + ~5 fma-pipe.
__device__ __forceinline__ float softplus_f(float z) {
  return fmaxf(z, 0.f) + __logf(1.f + __expf(-fabsf(z)));
}

// ---------------------------------------------------------------------------
// Kernel 2: main fused kernel. grid (Q/TQ, P/TP) = (32,32), block 256.
// Each CTA computes a 32x32 tile of m = sum_s softplus(pr+pe)*w2, applies
// leaky-relu, and multiplies into x for all 8 batches.
// Micro-tile per thread: 2p x 2q (q strided by 16 for coalescing).
// ---------------------------------------------------------------------------
__global__ __launch_bounds__(256) void adj_kernel(
    const float* __restrict__ x, const float* __restrict__ w2,
    float* __restrict__ out) {
  __shared__ float pr_t[S_DIM * PADP];  // [s][p], pad -> conflict-free
  __shared__ float pe_t[S_DIM * PADQ];  // [s][q]
  __shared__ float w2s[S_DIM];

  const int tid = threadIdx.x;
  const int p0 = blockIdx.y * TP;
  const int q0 = blockIdx.x * TQ;

  // Load tiles transposed. Global reads coalesced over s; smem writes hit
  // consecutive banks because row stride PADP/PADQ is odd (33 % 32 == 1).
#pragma unroll
  for (int i = tid; i < TP * S_DIM; i += 256) {
    int p = i >> 7, s = i & (S_DIM - 1);
    pr_t[s * PADP + p] = g_pr[(p0 + p) * S_DIM + s];
  }
#pragma unroll
  for (int i = tid; i < TQ * S_DIM; i += 256) {
    int q = i >> 7, s = i & (S_DIM - 1);
    pe_t[s * PADQ + q] = g_pe[(q0 + q) * S_DIM + s];
  }
  if (tid < S_DIM) w2s[tid] = w2[tid];
  __syncthreads();

  const int qi = tid & 15;        // q within tile: qi and qi+16
  const int pb = (tid >> 4) * 2;  // p within tile: pb and pb+1

  float acc00 = 0.f, acc01 = 0.f, acc10 = 0.f, acc11 = 0.f;

#pragma unroll 4
  for (int s = 0; s < S_DIM; ++s) {
    const float w = w2s[s];
    const float pr0 = pr_t[s * PADP + pb];
    const float pr1 = pr_t[s * PADP + pb + 1];
    const float pe0 = pe_t[s * PADQ + qi];
    const float pe1 = pe_t[s * PADQ + qi + 16];
    acc00 = fmaf(softplus_f(pr0 + pe0), w, acc00);
    acc01 = fmaf(softplus_f(pr0 + pe1), w, acc01);
    acc10 = fmaf(softplus_f(pr1 + pe0), w, acc10);
    acc11 = fmaf(softplus_f(pr1 + pe1), w, acc11);
  }

  // leaky relu (alpha = 0.1)
  const float a00 = acc00 >= 0.f ? acc00 : 0.1f * acc00;
  const float a01 = acc01 >= 0.f ? acc01 : 0.1f * acc01;
  const float a10 = acc10 >= 0.f ? acc10 : 0.1f * acc10;
  const float a11 = acc11 >= 0.f ? acc11 : 0.1f * acc11;

  // Broadcast-multiply into x over batches. Lanes 0..15 cover 16 consecutive
  // q addresses per access -> 64B coalesced segments.
  const size_t base0 = (size_t)(p0 + pb) * Q_DIM + (q0 + qi);
  const size_t base1 = base0 + Q_DIM;
  const size_t plane = (size_t)P_DIM * Q_DIM;
#pragma unroll
  for (int b = 0; b < B_DIM; ++b) {
    const size_t o = (size_t)b * plane;
    out[o + base0]      = a00 * x[o + base0];
    out[o + base0 + 16] = a01 * x[o + base0 + 16];
    out[o + base1]      = a10 * x[o + base1];
    out[o + base1 + 16] = a11 * x[o + base1 + 16];
  }
}

extern "C" void kernel_launch(void* const* d_in, const int* in_sizes, int n_in,
                              void* d_out, int out_size) {
  const float* x       = (const float*)d_in[0];  // [8,1024,1024]
  const float* product = (const float*)d_in[1];  // [1024,128]
  const float* person  = (const float*)d_in[2];  // [1024,128]
  const float* w1      = (const float*)d_in[3];  // [256,128]
  const float* w2      = (const float*)d_in[4];  // [128,1]
  float* out = (float*)d_out;                    // [8,1024,1024]

  proj_kernel<<<dim3(P_DIM, 2), S_DIM>>>(product, person, w1);
  adj_kernel<<<dim3(Q_DIM / TQ, P_DIM / TP), 256>>>(x, w2, out);
}

// round 4
// speedup vs baseline: 1.5406x; 1.5406x over previous
#include <cuda_runtime.h>
#include <cstdint>

#define P_DIM 1024
#define Q_DIM 1024
#define S_DIM 128
#define B_DIM 8

#define TP 64   // p-tile
#define TQ 16   // q-tile
#define NTHR 128

// Transposed projections + rank-1 vectors (device-global scratch)
__device__ __align__(16) float g_pr_t[S_DIM][P_DIM];  // (product @ w1[:S])^T
__device__ __align__(16) float g_pe_t[S_DIM][Q_DIM];  // (person  @ w1[S:])^T
__device__ __align__(16) float g_a[P_DIM];            // sum_s pr[p,s]*w2[s]
__device__ __align__(16) float g_b[Q_DIM];            // sum_s pe[q,s]*w2[s]

// ---------------- packed f32x2 helpers (sm_100a) ----------------
__device__ __forceinline__ uint64_t fdup(float f) {
  uint64_t r;
  asm("mov.b64 %0, {%1, %1};" : "=l"(r) : "r"(__float_as_uint(f)));
  return r;
}
__device__ __forceinline__ uint64_t addx2(uint64_t a, uint64_t b) {
  uint64_t d; asm("add.rn.f32x2 %0, %1, %2;" : "=l"(d) : "l"(a), "l"(b)); return d;
}
__device__ __forceinline__ uint64_t mulx2(uint64_t a, uint64_t b) {
  uint64_t d; asm("mul.rn.f32x2 %0, %1, %2;" : "=l"(d) : "l"(a), "l"(b)); return d;
}
__device__ __forceinline__ uint64_t fmax2(uint64_t a, uint64_t b, uint64_t c) {
  uint64_t d; asm("fma.rn.f32x2 %0, %1, %2, %3;" : "=l"(d) : "l"(a), "l"(b), "l"(c)); return d;
}
__device__ __forceinline__ float2 unpk(uint64_t v) {
  uint32_t lo, hi;
  asm("mov.b64 {%0, %1}, %2;" : "=r"(lo), "=r"(hi) : "l"(v));
  return make_float2(__uint_as_float(lo), __uint_as_float(hi));
}
__device__ __forceinline__ uint64_t pk(float lo, float hi) {
  uint64_t r;
  asm("mov.b64 %0, {%1, %2};" : "=l"(r) : "r"(__float_as_uint(lo)), "r"(__float_as_uint(hi)));
  return r;
}

// ---------------------------------------------------------------------------
// Prologue: blocked projection (8 rows per CTA) + rank-1 reductions.
// grid (128, 2), block 128. y==0 -> product/g_pr_t/g_a, y==1 -> person/.../g_b
// ---------------------------------------------------------------------------
__global__ __launch_bounds__(NTHR) void proj_kernel(
    const float* __restrict__ product, const float* __restrict__ person,
    const float* __restrict__ w1, const float* __restrict__ w2) {
  __shared__ float rows[8][S_DIM];
  __shared__ float red[8][4];
  const int s = threadIdx.x;
  const int row0 = blockIdx.x * 8;
  const float* src; const float* wb;
  if (blockIdx.y == 0) { src = product; wb = w1; }
  else                 { src = person;  wb = w1 + S_DIM * S_DIM; }

#pragma unroll
  for (int r = 0; r < 8; ++r) rows[r][s] = src[(row0 + r) * S_DIM + s];
  __syncthreads();

  float acc[8] = {0.f, 0.f, 0.f, 0.f, 0.f, 0.f, 0.f, 0.f};
#pragma unroll 4
  for (int k = 0; k < S_DIM; ++k) {
    const float w = wb[k * S_DIM + s];  // coalesced over s
#pragma unroll
    for (int r = 0; r < 8; ++r) acc[r] = fmaf(rows[r][k], w, acc[r]);
  }

  const float wv = w2[s];
#pragma unroll
  for (int r = 0; r < 8; ++r) {
    if (blockIdx.y == 0) g_pr_t[s][row0 + r] = acc[r];
    else                 g_pe_t[s][row0 + r] = acc[r];
    float v = acc[r] * wv;
#pragma unroll
    for (int o = 16; o > 0; o >>= 1) v += __shfl_down_sync(0xffffffffu, v, o);
    if ((s & 31) == 0) red[r][s >> 5] = v;
  }
  __syncthreads();
  if (s < 8) {
    const float t = red[s][0] + red[s][1] + red[s][2] + red[s][3];
    if (blockIdx.y == 0) g_a[row0 + s] = t;
    else                 g_b[row0 + s] = t;
  }
}

// softplus(z) = z/2 + g(z^2), g(v) = ln2 + v/8 - v^2/192 + v^3/2880 - 17v^4/645120
// One packed step: acc += g((pr+pe)^2) * w   (z/2 part is rank-1, added in epilogue)
__device__ __forceinline__ uint64_t sp_step(float pr, uint64_t pe2, uint64_t wv,
                                            uint64_t acc, uint64_t c0, uint64_t c1,
                                            uint64_t c2, uint64_t c3, uint64_t c4) {
  const uint64_t z = addx2(fdup(pr), pe2);
  const uint64_t v = mulx2(z, z);
  uint64_t t = fmax2(c4, v, c3);
  t = fmax2(t, v, c2);
  t = fmax2(t, v, c1);
  t = fmax2(t, v, c0);
  return fmax2(t, wv, acc);
}

// ---------------------------------------------------------------------------
// Main fused kernel. grid (Q/TQ, P/TP) = (64, 16) = 1024 CTAs, block 128.
// Micro-tile per thread: 4p x 1 packed q-pair (qi -> q = 2*qi, 2*qi+1).
// ---------------------------------------------------------------------------
__global__ __launch_bounds__(NTHR) void adj_kernel(
    const float* __restrict__ x, const float* __restrict__ w2,
    float* __restrict__ out) {
  __shared__ float spr[S_DIM][TP];       // 32 KB
  __shared__ float spe[S_DIM][TQ];       //  8 KB
  __shared__ float2 spw[S_DIM];          //  1 KB (w2 duplicated for packed fma)

  const int tid = threadIdx.x;
  const int p0 = blockIdx.y * TP;
  const int q0 = blockIdx.x * TQ;

  // Load tiles (sources already transposed -> coalesced reads, conflict-free writes)
#pragma unroll
  for (int k = 0; k < (TP * S_DIM) / NTHR; ++k) {
    const int i = tid + k * NTHR;
    spr[i >> 6][i & (TP - 1)] = g_pr_t[i >> 6][p0 + (i & (TP - 1))];
  }
#pragma unroll
  for (int k = 0; k < (TQ * S_DIM) / NTHR; ++k) {
    const int i = tid + k * NTHR;
    spe[i >> 4][i & (TQ - 1)] = g_pe_t[i >> 4][q0 + (i & (TQ - 1))];
  }
  spw[tid] = make_float2(w2[tid], w2[tid]);
  __syncthreads();

  const int qi = tid & 7;        // q pair: q0 + 2*qi + {0,1}
  const int pi = tid >> 3;       // p: p0 + 4*pi + {0,1,2,3}
  const int qi2 = qi * 2, pi4 = pi * 4;

  const uint64_t c0 = fdup(0.69314718f);
  const uint64_t c1 = fdup(0.125f);
  const uint64_t c2 = fdup(-5.2083333e-3f);
  const uint64_t c3 = fdup(3.4722222e-4f);
  const uint64_t c4 = fdup(-2.6351716e-5f);

  uint64_t a0 = 0ull, a1 = 0ull, a2 = 0ull, a3 = 0ull;  // packed (q, q+1) accs

#pragma unroll 4
  for (int s = 0; s < S_DIM; ++s) {
    const uint64_t pe2 = *reinterpret_cast<const uint64_t*>(&spe[s][qi2]);
    const float4 pr4 = *reinterpret_cast<const float4*>(&spr[s][pi4]);
    const uint64_t wv = *reinterpret_cast<const uint64_t*>(&spw[s]);
    a0 = sp_step(pr4.x, pe2, wv, a0, c0, c1, c2, c3, c4);
    a1 = sp_step(pr4.y, pe2, wv, a1, c0, c1, c2, c3, c4);
    a2 = sp_step(pr4.z, pe2, wv, a2, c0, c1, c2, c3, c4);
    a3 = sp_step(pr4.w, pe2, wv, a3, c0, c1, c2, c3, c4);
  }

  // Epilogue: add rank-1 z/2 term, leaky-relu, broadcast-multiply into x.
  const float4 av = *reinterpret_cast<const float4*>(&g_a[p0 + pi4]);
  const float2 bv = *reinterpret_cast<const float2*>(&g_b[q0 + qi2]);

  uint64_t accs[4] = {a0, a1, a2, a3};
  const float as[4] = {av.x, av.y, av.z, av.w};

  const int plane = P_DIM * Q_DIM;
  const uint64_t* xv = reinterpret_cast<const uint64_t*>(x);
  uint64_t* ov = reinterpret_cast<uint64_t*>(out);

#pragma unroll
  for (int k = 0; k < 4; ++k) {
    const float2 g = unpk(accs[k]);
    float m0 = fmaf(0.5f, as[k] + bv.x, g.x);
    float m1 = fmaf(0.5f, as[k] + bv.y, g.y);
    m0 = m0 >= 0.f ? m0 : 0.1f * m0;
    m1 = m1 >= 0.f ? m1 : 0.1f * m1;
    const uint64_t adj = pk(m0, m1);
    const int base = ((p0 + pi4 + k) * Q_DIM + q0 + qi2) >> 1;  // in float2 units
#pragma unroll
    for (int b = 0; b < B_DIM; ++b) {
      const int o = (b * plane >> 1) + base;
      ov[o] = mulx2(adj, xv[o]);
    }
  }
}

extern "C" void kernel_launch(void* const* d_in, const int* in_sizes, int n_in,
                              void* d_out, int out_size) {
  const float* x       = (const float*)d_in[0];  // [8,1024,1024]
  const float* product = (const float*)d_in[1];  // [1024,128]
  const float* person  = (const float*)d_in[2];  // [1024,128]
  const float* w1      = (const float*)d_in[3];  // [256,128]
  const float* w2      = (const float*)d_in[4];  // [128,1]
  float* out = (float*)d_out;                    // [8,1024,1024]

  proj_kernel<<<dim3(P_DIM / 8, 2), NTHR>>>(product, person, w1, w2);
  adj_kernel<<<dim3(Q_DIM / TQ, P_DIM / TP), NTHR>>>(x, w2, out);
}

// round 7
// speedup vs baseline: 2.0016x; 1.2992x over previous
#include <cuda_runtime.h>
#include <cstdint>

#define P_DIM 1024
#define Q_DIM 1024
#define S_DIM 128
#define B_DIM 8

#define TP 32   // p-tile
#define TQ 32   // q-tile
#define NTHR 128

// Transposed projections + rank-1 vectors (device-global scratch)
__device__ __align__(16) float g_pr_t[S_DIM][P_DIM];  // (product @ w1[:S])^T
__device__ __align__(16) float g_pe_t[S_DIM][Q_DIM];  // (person  @ w1[S:])^T
__device__ __align__(16) float g_a[P_DIM];  // sum_s pr*w2 + 2*ln2*sum(w2)
__device__ __align__(16) float g_b[Q_DIM];  // sum_s pe*w2

// ---------------- packed f32x2 helpers (sm_100a) ----------------
__device__ __forceinline__ uint64_t fdup(float f) {
  uint64_t r;
  asm("mov.b64 %0, {%1, %1};" : "=l"(r) : "r"(__float_as_uint(f)));
  return r;
}
__device__ __forceinline__ uint64_t addx2(uint64_t a, uint64_t b) {
  uint64_t d; asm("add.rn.f32x2 %0, %1, %2;" : "=l"(d) : "l"(a), "l"(b)); return d;
}
__device__ __forceinline__ uint64_t mulx2(uint64_t a, uint64_t b) {
  uint64_t d; asm("mul.rn.f32x2 %0, %1, %2;" : "=l"(d) : "l"(a), "l"(b)); return d;
}
__device__ __forceinline__ uint64_t fmax2(uint64_t a, uint64_t b, uint64_t c) {
  uint64_t d; asm("fma.rn.f32x2 %0, %1, %2, %3;" : "=l"(d) : "l"(a), "l"(b), "l"(c)); return d;
}
__device__ __forceinline__ float2 unpk(uint64_t v) {
  uint32_t lo, hi;
  asm("mov.b64 {%0, %1}, %2;" : "=r"(lo), "=r"(hi) : "l"(v));
  return make_float2(__uint_as_float(lo), __uint_as_float(hi));
}
__device__ __forceinline__ uint64_t pk(float lo, float hi) {
  uint64_t r;
  asm("mov.b64 %0, {%1, %2};" : "=l"(r) : "r"(__float_as_uint(lo)), "r"(__float_as_uint(hi)));
  return r;
}

// ---------------------------------------------------------------------------
// Prologue: blocked projection (8 rows per CTA) + rank-1 reductions.
// grid (128, 2), block 128. y==0 -> product/g_pr_t/g_a, y==1 -> person/.../g_b
// g_a additionally absorbs the rank-0 term 2*ln2*sum(w2).
// ---------------------------------------------------------------------------
__global__ __launch_bounds__(NTHR) void proj_kernel(
    const float* __restrict__ product, const float* __restrict__ person,
    const float* __restrict__ w1, const float* __restrict__ w2) {
  __shared__ float rows[8][S_DIM];
  __shared__ float red[8][4];
  __shared__ float wpart[4];
  const int s = threadIdx.x;
  const int row0 = blockIdx.x * 8;
  const float* src; const float* wb;
  if (blockIdx.y == 0) { src = product; wb = w1; }
  else                 { src = person;  wb = w1 + S_DIM * S_DIM; }

#pragma unroll
  for (int r = 0; r < 8; ++r) rows[r][s] = src[(row0 + r) * S_DIM + s];

  const float wv = w2[s];
  {  // block-reduce sum(w2) into wpart
    float t = wv;
#pragma unroll
    for (int o = 16; o > 0; o >>= 1) t += __shfl_down_sync(0xffffffffu, t, o);
    if ((s & 31) == 0) wpart[s >> 5] = t;
  }
  __syncthreads();

  float acc[8] = {0.f, 0.f, 0.f, 0.f, 0.f, 0.f, 0.f, 0.f};
#pragma unroll 4
  for (int k = 0; k < S_DIM; ++k) {
    const float w = wb[k * S_DIM + s];  // coalesced over s
#pragma unroll
    for (int r = 0; r < 8; ++r) acc[r] = fmaf(rows[r][k], w, acc[r]);
  }

#pragma unroll
  for (int r = 0; r < 8; ++r) {
    if (blockIdx.y == 0) g_pr_t[s][row0 + r] = acc[r];
    else                 g_pe_t[s][row0 + r] = acc[r];
    float v = acc[r] * wv;
#pragma unroll
    for (int o = 16; o > 0; o >>= 1) v += __shfl_down_sync(0xffffffffu, v, o);
    if ((s & 31) == 0) red[r][s >> 5] = v;
  }
  __syncthreads();
  if (s < 8) {
    const float t = red[s][0] + red[s][1] + red[s][2] + red[s][3];
    if (blockIdx.y == 0) {
      const float W = wpart[0] + wpart[1] + wpart[2] + wpart[3];
      g_a[row0 + s] = t + 1.38629436f * W;  // + 2*ln2*sum(w2) (rank-0 term)
    } else {
      g_b[row0 + s] = t;
    }
  }
}

// One packed step: acc += w * (v/8 - v^2/192), v = (pr+pe)^2, coeffs pre-folded.
__device__ __forceinline__ uint64_t sp_step(uint64_t prd, uint64_t pe2,
                                            uint64_t cw1, uint64_t cw2,
                                            uint64_t acc) {
  const uint64_t z = addx2(prd, pe2);
  const uint64_t v = mulx2(z, z);
  const uint64_t u = fmax2(cw2, v, cw1);
  return fmax2(u, v, acc);
}

// ---------------------------------------------------------------------------
// Main fused kernel. grid (Q/TQ, P/TP) = (32, 32) = 1024 CTAs, block 128.
// Micro-tile per thread: 2p x 2 packed q-pairs (4 q values).
// softplus(z) = z/2 + ln2 + z^2/8 - z^4/192 + O(z^6); z/2 and ln2 terms are
// rank-1/rank-0 (in g_a/g_b), poly part accumulated here with folded w2.
// ---------------------------------------------------------------------------
__global__ __launch_bounds__(NTHR, 6) void adj_kernel(
    const float* __restrict__ x, const float* __restrict__ w2,
    float* __restrict__ out) {
  __shared__ float spr[S_DIM][TP];    // 16 KB
  __shared__ float spe[S_DIM][TQ];    // 16 KB
  __shared__ float4 scw[S_DIM];       //  2 KB: {w/8, w/8, -w/192, -w/192}

  const int tid = threadIdx.x;
  const int p0 = blockIdx.y * TP;
  const int q0 = blockIdx.x * TQ;

  // Tile loads (float4 vectorized; sources transposed -> coalesced)
#pragma unroll
  for (int k = 0; k < (TP * S_DIM) / (NTHR * 4); ++k) {
    const int i = tid + k * NTHR;               // float4 index
    const int s = i >> 3, j = i & 7;            // 8 float4 per row
    *reinterpret_cast<float4*>(&spr[s][j * 4]) =
        *reinterpret_cast<const float4*>(&g_pr_t[s][p0 + j * 4]);
  }
#pragma unroll
  for (int k = 0; k < (TQ * S_DIM) / (NTHR * 4); ++k) {
    const int i = tid + k * NTHR;
    const int s = i >> 3, j = i & 7;
    *reinterpret_cast<float4*>(&spe[s][j * 4]) =
        *reinterpret_cast<const float4*>(&g_pe_t[s][q0 + j * 4]);
  }
  {
    const float w = w2[tid];
    scw[tid] = make_float4(0.125f * w, 0.125f * w,
                           -5.2083333e-3f * w, -5.2083333e-3f * w);
  }
  __syncthreads();

  const int qi = tid & 7;    // q pairs at q0 + 2*qi and q0 + 2*qi + 16
  const int pi = tid >> 3;   // p at p0 + 2*pi and p0 + 2*pi + 1
  const int qi2 = qi * 2, pi2 = pi * 2;

  uint64_t a00 = 0ull, a01 = 0ull, a10 = 0ull, a11 = 0ull;

#pragma unroll 4
  for (int s = 0; s < S_DIM; ++s) {
    const uint64_t peA = *reinterpret_cast<const uint64_t*>(&spe[s][qi2]);
    const uint64_t peB = *reinterpret_cast<const uint64_t*>(&spe[s][qi2 + 16]);
    const float2 pr = *reinterpret_cast<const float2*>(&spr[s][pi2]);
    const ulonglong2 cw = *reinterpret_cast<const ulonglong2*>(&scw[s]);
    const uint64_t prx = fdup(pr.x);
    const uint64_t pry = fdup(pr.y);
    a00 = sp_step(prx, peA, cw.x, cw.y, a00);
    a01 = sp_step(prx, peB, cw.x, cw.y, a01);
    a10 = sp_step(pry, peA, cw.x, cw.y, a10);
    a11 = sp_step(pry, peB, cw.x, cw.y, a11);
  }

  // Epilogue: m = acc + 0.5*(a'_p + b_q); leaky relu; multiply into x.
  const float2 av = *reinterpret_cast<const float2*>(&g_a[p0 + pi2]);
  const float2 bA = *reinterpret_cast<const float2*>(&g_b[q0 + qi2]);
  const float2 bB = *reinterpret_cast<const float2*>(&g_b[q0 + qi2 + 16]);

  const uint64_t accs[4] = {a00, a01, a10, a11};
  const float pa[4] = {av.x, av.x, av.y, av.y};
  const float2 qb[4] = {bA, bB, bA, bB};
  const int coff[4] = {0, 8, 0, 8};            // float2 column offset
  const int roff[4] = {0, 0, 512, 512};        // float2 row offset (Q/2)

  const int plane2 = (P_DIM * Q_DIM) >> 1;
  const uint64_t* xv = reinterpret_cast<const uint64_t*>(x);
  uint64_t* ov = reinterpret_cast<uint64_t*>(out);
  const int base = (((p0 + pi2) * Q_DIM + q0 + qi2) >> 1);

#pragma unroll
  for (int k = 0; k < 4; ++k) {
    const float2 g = unpk(accs[k]);
    float m0 = fmaf(0.5f, pa[k] + qb[k].x, g.x);
    float m1 = fmaf(0.5f, pa[k] + qb[k].y, g.y);
    m0 = m0 >= 0.f ? m0 : 0.1f * m0;
    m1 = m1 >= 0.f ? m1 : 0.1f * m1;
    const uint64_t adj = pk(m0, m1);
    const int bidx = base + roff[k] + coff[k];
#pragma unroll
    for (int b = 0; b < B_DIM; ++b) {
      const int o = b * plane2 + bidx;
      ov[o] = mulx2(adj, xv[o]);
    }
  }
}

extern "C" void kernel_launch(void* const* d_in, const int* in_sizes, int n_in,
                              void* d_out, int out_size) {
  const float* x       = (const float*)d_in[0];  // [8,1024,1024]
  const float* product = (const float*)d_in[1];  // [1024,128]
  const float* person  = (const float*)d_in[2];  // [1024,128]
  const float* w1      = (const float*)d_in[3];  // [256,128]
  const float* w2      = (const float*)d_in[4];  // [128,1]
  float* out = (float*)d_out;                    // [8,1024,1024]

  proj_kernel<<<dim3(P_DIM / 8, 2), NTHR>>>(product, person, w1, w2);
  adj_kernel<<<dim3(Q_DIM / TQ, P_DIM / TP), NTHR>>>(x, w2, out);
}